// round 1
// baseline (speedup 1.0000x reference)
#include <cuda_runtime.h>

#define EPSK 1e-7f

constexpr int Bn = 2, Hh = 192, Ww = 192, HQ = 384;

// Scratch (no allocations allowed -> __device__ globals)
__device__ float g_a4[Bn * 96 * 96 * 32];
__device__ float g_a32[Bn * 24 * 24 * 32];
__device__ float g_X[Bn * Hh * Ww * 96];     // concat of a2 | up(a4) | up(a32)
__device__ float g_aspp[Bn * Hh * Ww * 96];  // conv3x3 output
__device__ float g_P[Bn * Hh * Ww * 64];     // aspp @ mw0[:96] + mb0

// ---------------------------------------------------------------------------
// 1x1 conv + ReLU. One warp per pixel, lane = output channel (Cout == 32).
// ---------------------------------------------------------------------------
__global__ void conv1x1_kernel(const float* __restrict__ in, const float* __restrict__ w,
                               const float* __restrict__ bias, float* __restrict__ out,
                               int npix, int Cin, int outStride, int outOff)
{
    extern __shared__ float ws[];  // Cin*32 floats
    int tid = threadIdx.x;
    for (int i = tid; i < Cin * 32; i += blockDim.x) ws[i] = w[i];
    __syncthreads();
    int warp = tid >> 5, lane = tid & 31;
    int p = blockIdx.x * (blockDim.x >> 5) + warp;
    if (p >= npix) return;
    const float* ip = in + (size_t)p * Cin;
    float acc = bias[lane];
#pragma unroll 4
    for (int k = 0; k < Cin; k++) acc += ip[k] * ws[k * 32 + lane];
    out[(size_t)p * outStride + outOff + lane] = fmaxf(acc, 0.0f);
}

// ---------------------------------------------------------------------------
// Bilinear upsample (half-pixel centers, edge clamp == jax renormalize) of a
// 32-channel map to 192x192, written into the concat buffer at chOff.
// ---------------------------------------------------------------------------
__global__ void upsample_kernel(const float* __restrict__ in, float* __restrict__ X,
                                int inH, int inW, int chOff)
{
    int idx = blockIdx.x * blockDim.x + threadIdx.x;  // Bn*Hh*Ww*8 exact
    int c4 = idx & 7;
    int pix = idx >> 3;
    int x = pix % Ww;
    int t = pix / Ww;
    int y = t % Hh;
    int b = t / Hh;

    float sy = (y + 0.5f) * (float)inH / (float)Hh - 0.5f;
    float sx = (x + 0.5f) * (float)inW / (float)Ww - 0.5f;
    float fy0 = floorf(sy), fx0 = floorf(sx);
    float fy = sy - fy0, fx = sx - fx0;
    int y0 = (int)fy0, x0 = (int)fx0;
    int y1 = min(y0 + 1, inH - 1), x1 = min(x0 + 1, inW - 1);
    y0 = max(y0, 0);
    x0 = max(x0, 0);

    const float4* ip = (const float4*)in;
    float4 v00 = ip[(((size_t)b * inH + y0) * inW + x0) * 8 + c4];
    float4 v01 = ip[(((size_t)b * inH + y0) * inW + x1) * 8 + c4];
    float4 v10 = ip[(((size_t)b * inH + y1) * inW + x0) * 8 + c4];
    float4 v11 = ip[(((size_t)b * inH + y1) * inW + x1) * 8 + c4];
    float w00 = (1.f - fy) * (1.f - fx), w01 = (1.f - fy) * fx;
    float w10 = fy * (1.f - fx), w11 = fy * fx;
    float4 r;
    r.x = v00.x * w00 + v01.x * w01 + v10.x * w10 + v11.x * w11;
    r.y = v00.y * w00 + v01.y * w01 + v10.y * w10 + v11.y * w11;
    r.z = v00.z * w00 + v01.z * w01 + v10.z * w10 + v11.z * w11;
    r.w = v00.w * w00 + v01.w * w01 + v10.w * w10 + v11.w * w11;
    *(float4*)(X + (((size_t)b * Hh + y) * Ww + x) * 96 + chOff + c4 * 4) = r;
}

// ---------------------------------------------------------------------------
// 3x3 conv (zero pad SAME) 96->96 + bias + ReLU.
// Block: 8x8 spatial tile x 32 output channels; ic chunked by 16 (6 chunks).
// Warp = one output row, lanes = output channels (ws reads conflict-free,
// in_s reads uniform -> broadcast).
// ---------------------------------------------------------------------------
__global__ void __launch_bounds__(256)
conv3x3_kernel(const float* __restrict__ X, const float* __restrict__ wf,
               const float* __restrict__ bf, float* __restrict__ out)
{
    __shared__ float in_s[10 * 10 * 16];
    __shared__ float ws[9 * 16 * 32];
    int tx0 = blockIdx.x * 8, ty0 = blockIdx.y * 8;
    int b = blockIdx.z / 3, ocg = blockIdx.z % 3;
    int tid = threadIdx.x;
    int oc = tid & 31, row = tid >> 5;

    float acc[8];
#pragma unroll
    for (int i = 0; i < 8; i++) acc[i] = 0.0f;

#pragma unroll 1
    for (int icc = 0; icc < 6; icc++) {
        int icb = icc * 16;
        __syncthreads();
        // input tile 10x10x16 (zero padded)
        for (int i = tid; i < 1600; i += 256) {
            int ic = i & 15;
            int rp = i >> 4;
            int rx = rp % 10, ry = rp / 10;
            int gy = ty0 + ry - 1, gx = tx0 + rx - 1;
            float v = 0.0f;
            if ((unsigned)gy < (unsigned)Hh && (unsigned)gx < (unsigned)Ww)
                v = X[(((size_t)b * Hh + gy) * Ww + gx) * 96 + icb + ic];
            in_s[rp * 16 + ic] = v;
        }
        // weights 9x16x32
        for (int i = tid; i < 4608; i += 256) {
            int o = i & 31;
            int r = i >> 5;
            int ic = r & 15;
            int kk = r >> 4;  // 0..8 == dy*3+dx
            ws[i] = wf[((size_t)kk * 96 + icb + ic) * 96 + ocg * 32 + o];
        }
        __syncthreads();
#pragma unroll
        for (int dy = 0; dy < 3; dy++) {
#pragma unroll
            for (int ic = 0; ic < 16; ic++) {
                float xr[10];
#pragma unroll
                for (int t = 0; t < 10; t++) xr[t] = in_s[((row + dy) * 10 + t) * 16 + ic];
#pragma unroll
                for (int dx = 0; dx < 3; dx++) {
                    float w = ws[((dy * 3 + dx) * 16 + ic) * 32 + oc];
#pragma unroll
                    for (int col = 0; col < 8; col++) acc[col] += xr[col + dx] * w;
                }
            }
        }
    }
    float bb = bf[ocg * 32 + oc];
#pragma unroll
    for (int col = 0; col < 8; col++) {
        int gy = ty0 + row, gx = tx0 + col;
        out[(((size_t)b * Hh + gy) * Ww + gx) * 96 + ocg * 32 + oc] = fmaxf(acc[col] + bb, 0.0f);
    }
}

// ---------------------------------------------------------------------------
// Per-pixel MLP-layer-1 feature projection: P = aspp @ mw0[0:96] + mb0.
// One warp per pixel; lane computes outputs (lane, lane+32).
// ---------------------------------------------------------------------------
__global__ void proj_kernel(const float* __restrict__ aspp, const float* __restrict__ mw0,
                            const float* __restrict__ mb0, float* __restrict__ P)
{
    __shared__ float ws[96 * 64];
    int tid = threadIdx.x;
    for (int i = tid; i < 96 * 64; i += 256) ws[i] = mw0[i];
    __syncthreads();
    int warp = tid >> 5, lane = tid & 31;
    int p = blockIdx.x * 8 + warp;  // 73728 pixels = 9216 blocks * 8
    const float* ip = aspp + (size_t)p * 96;
    float a0 = mb0[lane], a1 = mb0[lane + 32];
#pragma unroll 4
    for (int k = 0; k < 96; k++) {
        float x = ip[k];
        a0 += x * ws[k * 64 + lane];
        a1 += x * ws[k * 64 + lane + 32];
    }
    P[(size_t)p * 64 + lane] = a0;
    P[(size_t)p * 64 + lane + 32] = a1;
}

// ---------------------------------------------------------------------------
// Decode: one thread per query. 4 corners: nearest gather of projected P,
// add the 6 "extra" input contributions via mw0[96:102], ReLU, 64x64 layer,
// 64->1 layer, area-weighted blend (areas paired in reverse corner order).
// ---------------------------------------------------------------------------
__global__ void __launch_bounds__(256)
decode_kernel(const float* __restrict__ P, const float* __restrict__ coords,
              const float* __restrict__ cells, const float* __restrict__ mw0,
              const float* __restrict__ mw1, const float* __restrict__ mb1,
              const float* __restrict__ mw2, const float* __restrict__ mb2,
              float* __restrict__ out)
{
    __shared__ __align__(16) float sw1[64 * 64];
    __shared__ __align__(16) float sw0e[6 * 64];
    __shared__ float sb1[64];
    __shared__ float sw2[64];
    __shared__ float sb2s;
    int tid = threadIdx.x;
    for (int i = tid; i < 64 * 64; i += 256) sw1[i] = mw1[i];
    for (int i = tid; i < 6 * 64; i += 256) sw0e[i] = mw0[96 * 64 + i];
    if (tid < 64) { sb1[tid] = mb1[tid]; sw2[tid] = mw2[tid]; }
    if (tid == 0) sb2s = mb2[0];
    __syncthreads();

    int q = blockIdx.x * 256 + tid;  // 294912 = 1152 * 256 exact
    int b = q / (HQ * HQ);
    float cy = coords[2 * q], cx = coords[2 * q + 1];
    float clh = cells[2 * q] * (float)Hh, clw = cells[2 * q + 1] * (float)Ww;
    const float rr = 1.0f / (float)Hh;

    float preds[4], areas[4];
#pragma unroll 1
    for (int corner = 0; corner < 4; corner++) {
        float vy = (corner & 2) ? 1.0f : -1.0f;
        float vx = (corner & 1) ? 1.0f : -1.0f;
        float ccy = fminf(fmaxf(cy + vy * rr + EPSK, -1.0f + EPSK), 1.0f - EPSK);
        float ccx = fminf(fmaxf(cx + vx * rr + EPSK, -1.0f + EPSK), 1.0f - EPSK);
        int iy = (int)rintf((ccy + 1.0f) * (float)Hh / 2.0f - 0.5f);
        int ix = (int)rintf((ccx + 1.0f) * (float)Ww / 2.0f - 0.5f);
        iy = min(max(iy, 0), Hh - 1);
        ix = min(max(ix, 0), Ww - 1);
        float sampy = ((iy + 0.5f) / (float)Hh) * 2.0f - 1.0f;
        float sampx = ((ix + 0.5f) / (float)Ww) * 2.0f - 1.0f;
        float rely = (cy - sampy) * (float)Hh;
        float relx = (cx - sampx) * (float)Ww;

        float h0[64];
        const float4* p4 = (const float4*)(P + (((size_t)b * Hh + iy) * Ww + ix) * 64);
#pragma unroll
        for (int j = 0; j < 16; j++) {
            float4 v = p4[j];
            h0[4 * j + 0] = v.x; h0[4 * j + 1] = v.y;
            h0[4 * j + 2] = v.z; h0[4 * j + 3] = v.w;
        }
        float xs[6] = {rely, relx, cy, cx, clh, clw};
#pragma unroll
        for (int e = 0; e < 6; e++) {
            float xk = xs[e];
            const float4* wp = (const float4*)(sw0e + e * 64);
#pragma unroll
            for (int j = 0; j < 16; j++) {
                float4 w = wp[j];
                h0[4 * j + 0] += xk * w.x; h0[4 * j + 1] += xk * w.y;
                h0[4 * j + 2] += xk * w.z; h0[4 * j + 3] += xk * w.w;
            }
        }
        float h1[64];
#pragma unroll
        for (int j = 0; j < 64; j++) h1[j] = sb1[j];
#pragma unroll
        for (int k = 0; k < 64; k++) {
            float xk = fmaxf(h0[k], 0.0f);
            const float4* wp = (const float4*)(sw1 + k * 64);
#pragma unroll
            for (int j = 0; j < 16; j++) {
                float4 w = wp[j];
                h1[4 * j + 0] += xk * w.x; h1[4 * j + 1] += xk * w.y;
                h1[4 * j + 2] += xk * w.z; h1[4 * j + 3] += xk * w.w;
            }
        }
        float pr = sb2s;
#pragma unroll
        for (int j = 0; j < 64; j++) pr += fmaxf(h1[j], 0.0f) * sw2[j];
        preds[corner] = pr;
        areas[corner] = fabsf(rely * relx) + EPSK;
    }
    float num = preds[0] * areas[3] + preds[1] * areas[2] +
                preds[2] * areas[1] + preds[3] * areas[0];
    float den = areas[0] + areas[1] + areas[2] + areas[3];
    out[q] = num / den;
}

// ---------------------------------------------------------------------------
extern "C" void kernel_launch(void* const* d_in, const int* in_sizes, int n_in,
                              void* d_out, int out_size)
{
    const float* feats2  = (const float*)d_in[0];
    const float* feats4  = (const float*)d_in[1];
    const float* feats32 = (const float*)d_in[2];
    const float* coords  = (const float*)d_in[3];
    const float* cells   = (const float*)d_in[4];
    const float* w2  = (const float*)d_in[5];
    const float* b2  = (const float*)d_in[6];
    const float* w4  = (const float*)d_in[7];
    const float* b4  = (const float*)d_in[8];
    const float* w32 = (const float*)d_in[9];
    const float* b32 = (const float*)d_in[10];
    const float* wf  = (const float*)d_in[11];
    const float* bf  = (const float*)d_in[12];
    const float* mw0 = (const float*)d_in[13];
    const float* mb0 = (const float*)d_in[14];
    const float* mw1 = (const float*)d_in[15];
    const float* mb1 = (const float*)d_in[16];
    const float* mw2 = (const float*)d_in[17];
    const float* mb2 = (const float*)d_in[18];
    float* out = (float*)d_out;

    float *a4p, *a32p, *Xp, *asppp, *Pp;
    cudaGetSymbolAddress((void**)&a4p, g_a4);
    cudaGetSymbolAddress((void**)&a32p, g_a32);
    cudaGetSymbolAddress((void**)&Xp, g_X);
    cudaGetSymbolAddress((void**)&asppp, g_aspp);
    cudaGetSymbolAddress((void**)&Pp, g_P);

    // 1x1 convs (a2 goes straight into the concat buffer, channels 0..31)
    conv1x1_kernel<<<9216, 256, 64 * 32 * 4>>>(feats2, w2, b2, Xp, 73728, 64, 96, 0);
    conv1x1_kernel<<<2304, 256, 96 * 32 * 4>>>(feats4, w4, b4, a4p, 18432, 96, 32, 0);
    conv1x1_kernel<<<144, 256, 160 * 32 * 4>>>(feats32, w32, b32, a32p, 1152, 160, 32, 0);

    // bilinear upsample into concat channels 32..63 and 64..95
    upsample_kernel<<<2304, 256>>>(a4p, Xp, 96, 96, 32);
    upsample_kernel<<<2304, 256>>>(a32p, Xp, 24, 24, 64);

    // 3x3 conv + ReLU
    dim3 g3(24, 24, 6);
    conv3x3_kernel<<<g3, 256>>>(Xp, wf, bf, asppp);

    // per-pixel projection through MLP layer-1 feature block
    proj_kernel<<<9216, 256>>>(asppp, mw0, mb0, Pp);

    // per-query 4-corner decode + blend
    decode_kernel<<<1152, 256>>>(Pp, coords, cells, mw0, mw1, mb1, mw2, mb2, out);
}